// round 9
// baseline (speedup 1.0000x reference)
#include <cuda_runtime.h>
#include <cuda_bf16.h>
#include <math.h>

#define BB   64
#define LL   65536
#define NW   2047
#define WPB  128
#define BPB  16
#define SPAN_MAX 4128
#define HID  512
#define DM   256
#define SD   321

#define GRID2 256
#define SMEM2 36864   // 32KB W tile + 2.5KB A tile + slack

// ---------------- scratch (__device__ globals; no allocation allowed) -------
__device__ unsigned int g_hist_parts[BB * BPB * 256];
__device__ float g_went[BB * NW];
__device__ float g_feats[BB * SD];
__device__ float g_z1p[8][BB * HID];
__device__ float g_z2p[8][BB * HID];
__device__ float g_outp[8][BB * DM];
__device__ float g_a2[BB * HID];
__device__ float g_a3[BB * HID];
__device__ float g_sink;
__device__ unsigned int g_bar;

// ---------------- Kernel A: windowed entropies + global hist partials -------
__global__ void __launch_bounds__(256) win_kernel(const int* __restrict__ x) {
    const int b    = blockIdx.y;
    const int blk  = blockIdx.x;
    const int tid  = threadIdx.x;
    const int lane = tid & 31;
    const int warp = tid >> 5;

    if (blk == 0 && b == 0 && tid == 0) g_bar = 0u;   // reset grid barrier

    const int wstart = blk * WPB;
    const int wcount = min(WPB, NW - wstart);
    const int span   = (wcount - 1) * 32 + 64;
    const long base  = (long)b * LL + (long)blk * (WPB * 32);

    __shared__ __align__(16) unsigned char s_x[SPAN_MAX + 32];
    __shared__ unsigned int  s_hist[8][64];   // per-warp byte hist (256 B)
    __shared__ unsigned int  s_part[256];
    __shared__ float         s_lut[65];

    if (tid < 256) s_part[tid] = 0u;
    if (tid <= 64) {
        if (tid == 0) s_lut[0] = 0.0f;
        else {
            float p = (float)tid * (1.0f / 64.0f);
            float t = -(p * log2f(p + 1e-10f));
            s_lut[tid] = t / (float)tid;
        }
    }
    {
        const int4* xv = (const int4*)(x + base);
        uchar4* sv = (uchar4*)s_x;
        const int n4 = span >> 2;
        for (int i = tid; i < n4; i += 256) {
            int4 v = xv[i];
            sv[i] = make_uchar4((unsigned char)min(max(v.x, 0), 255),
                                (unsigned char)min(max(v.y, 0), 255),
                                (unsigned char)min(max(v.z, 0), 255),
                                (unsigned char)min(max(v.w, 0), 255));
        }
    }
    __syncthreads();

    for (int i = tid; i < 4096; i += 256)
        atomicAdd(&s_part[s_x[i]], 1u);

    unsigned int*  hist32 = s_hist[warp];
    unsigned char* hist8  = (unsigned char*)s_hist[warp];
    const unsigned lowmask = (1u << lane) - 1u;
    for (int wi = warp; wi < wcount; wi += 8) {
        const int off = wi * 32;
        hist32[lane]      = 0u;
        hist32[lane + 32] = 0u;
        __syncwarp();
        const int va = s_x[off + lane];
        const int vb = s_x[off + 32 + lane];
        // round A: counts of first 32 bytes (leader writes, race-free)
        const unsigned mA = __match_any_sync(0xffffffffu, va);
        if ((mA & lowmask) == 0u)
            hist8[va] = (unsigned char)__popc(mA);
        __syncwarp();
        // round B: add counts of second 32 bytes (leader RMW, distinct addrs)
        const unsigned mB = __match_any_sync(0xffffffffu, vb);
        if ((mB & lowmask) == 0u)
            hist8[vb] = (unsigned char)(hist8[vb] + __popc(mB));
        __syncwarp();
        float h = s_lut[hist8[va]] + s_lut[hist8[vb]];
        #pragma unroll
        for (int o = 16; o; o >>= 1) h += __shfl_xor_sync(0xffffffffu, h, o);
        if (lane == 0) g_went[b * NW + wstart + wi] = h;
    }

    __syncthreads();
    if (tid < 256) g_hist_parts[(b * BPB + blk) * 256 + tid] = s_part[tid];
}

// ---------------- persistent fused feat + MLP --------------------------------
__device__ __forceinline__ void grid_sync(unsigned int target) {
    __syncthreads();
    if (threadIdx.x == 0) {
        __threadfence();
        atomicAdd(&g_bar, 1u);
        volatile unsigned int* p = &g_bar;
        while (*p < target) {}
        __threadfence();
    }
    __syncthreads();
}

// GEMM jobs: tile 8r x 128c x CH-k, 2x2 per thread, 256 threads.
// MODE 1: A=g_feats K=321 CH=48 ct4 rg8 ks8 -> 256 jobs -> g_z1p[8]
// MODE 2: A=g_a2   K=512 CH=64 ct4 rg8 ks8 -> 256 jobs -> g_z2p[8]
// MODE 3: A=g_a3   K=512 CH=64 ct2 rg8 ks8 -> 128 jobs -> g_outp[8] (N=256)
template <int MODE>
__device__ void gemm_phase(const float* __restrict__ W, char* smem) {
    constexpr int CH = (MODE == 1) ? 48 : 64;
    constexpr int N  = (MODE == 3) ? DM : HID;
    constexpr int K  = (MODE == 1) ? SD : HID;

    const int job = blockIdx.x;
    if (MODE == 3 && job >= 128) return;
    int ct, rg, ks;
    if (MODE == 3) { ct = job & 1; rg = (job >> 1) & 7; ks = job >> 4; }
    else           { ct = job & 3; rg = (job >> 2) & 7; ks = job >> 5; }
    const int c0 = ct * 128, r0 = rg * 8, k0 = ks * CH;

    float* s_w = (float*)smem;                       // [CH][128]
    float* s_a = (float*)(smem + CH * 128 * 4);      // [CH][10]

    const int tid = threadIdx.x;

    // W tile: CH x 128, coalesced float4
    {
        const int kr0 = tid >> 5, c4 = (tid & 31) * 4;
        #pragma unroll
        for (int i = 0; i < CH / 8; i++) {
            const int kr = kr0 + i * 8;
            float4 v = make_float4(0.f, 0.f, 0.f, 0.f);
            if (MODE != 1 || (k0 + kr) < K)
                v = *(const float4*)&W[(long)(k0 + kr) * N + c0 + c4];
            *(float4*)&s_w[kr * 128 + c4] = v;
        }
    }
    // A tile: 8 rows x CH k, transposed
    {
        const float* A = (MODE == 1) ? g_feats : ((MODE == 2) ? g_a2 : g_a3);
        const int astr = (MODE == 1) ? SD : HID;
        for (int idx = tid; idx < 8 * CH; idx += 256) {
            const int r = idx / CH, k = idx - r * CH;
            float v = 0.f;
            if (MODE != 1 || (k0 + k) < K) v = A[(r0 + r) * astr + k0 + k];
            s_a[k * 10 + r] = v;
        }
    }
    __syncthreads();

    const int rp = tid >> 6, cp = tid & 63;
    float a00 = 0.f, a01 = 0.f, a10 = 0.f, a11 = 0.f;
    #pragma unroll 8
    for (int kk = 0; kk < CH; kk++) {
        const float2 wv = *(const float2*)&s_w[kk * 128 + cp * 2];
        const float2 av = *(const float2*)&s_a[kk * 10 + rp * 2];
        a00 = fmaf(av.x, wv.x, a00);
        a01 = fmaf(av.x, wv.y, a01);
        a10 = fmaf(av.y, wv.x, a10);
        a11 = fmaf(av.y, wv.y, a11);
    }
    __syncthreads();

    float* OP = (MODE == 1) ? &g_z1p[0][0] : ((MODE == 2) ? &g_z2p[0][0] : &g_outp[0][0]);
    const long base = (long)ks * (BB * N);
    const int r = r0 + rp * 2, cc = c0 + cp * 2;
    *(float2*)&OP[base + (long)r * N + cc]       = make_float2(a00, a01);
    *(float2*)&OP[base + (long)(r + 1) * N + cc] = make_float2(a10, a11);
}

// LN phase: blocks 0-63, block = row. 256 threads, 2 features each. 8 partials.
template <int LAYER>
__device__ void ln_phase(const float* __restrict__ bias,
                         const float* __restrict__ gam,
                         const float* __restrict__ bet, char* smem) {
    const float* P = (LAYER == 1) ? &g_z1p[0][0] : &g_z2p[0][0];
    float* outA    = (LAYER == 1) ? g_a2 : g_a3;
    float* s_r     = (float*)smem;      // [8]
    float* s_tot   = s_r + 8;

    const int r    = blockIdx.x;
    const int tid  = threadIdx.x;
    const int lane = tid & 31;
    const int wid  = tid >> 5;
    const int k1 = tid, k2 = tid + 256;

    float z1 = bias[k1], z2 = bias[k2];
    #pragma unroll
    for (int s = 0; s < 8; s++) {
        z1 += P[(long)s * (BB * HID) + r * HID + k1];
        z2 += P[(long)s * (BB * HID) + r * HID + k2];
    }

    float t = z1 + z2;
    #pragma unroll
    for (int o = 16; o; o >>= 1) t += __shfl_xor_sync(0xffffffffu, t, o);
    if (lane == 0) s_r[wid] = t;
    __syncthreads();
    if (tid == 0) {
        float u = 0.f;
        #pragma unroll
        for (int i = 0; i < 8; i++) u += s_r[i];
        *s_tot = u;
    }
    __syncthreads();
    const float mu = *s_tot * (1.0f / 512.0f);

    const float d1 = z1 - mu, d2 = z2 - mu;
    float v = d1 * d1 + d2 * d2;
    #pragma unroll
    for (int o = 16; o; o >>= 1) v += __shfl_xor_sync(0xffffffffu, v, o);
    if (lane == 0) s_r[wid] = v;
    __syncthreads();
    if (tid == 0) {
        float u = 0.f;
        #pragma unroll
        for (int i = 0; i < 8; i++) u += s_r[i];
        *s_tot = u;
    }
    __syncthreads();
    const float rstd = rsqrtf(*s_tot * (1.0f / 512.0f) + 1e-5f);

    outA[r * HID + k1] = fmaxf(d1 * rstd * gam[k1] + bet[k1], 0.0f);
    outA[r * HID + k2] = fmaxf(d2 * rstd * gam[k2] + bet[k2], 0.0f);
}

__global__ void __launch_bounds__(256, 2) mlp_fused2(
    const float* __restrict__ W1, const float* __restrict__ b1,
    const float* __restrict__ g1, const float* __restrict__ be1,
    const float* __restrict__ W2, const float* __restrict__ b2,
    const float* __restrict__ g2, const float* __restrict__ be2,
    const float* __restrict__ W3, const float* __restrict__ b3,
    float* __restrict__ out) {
    extern __shared__ __align__(16) char smem[];
    const int job = blockIdx.x;
    const int tid = threadIdx.x;

    // ---- phase A: features (blocks 0-63); others prefetch weights to L2 ----
    if (job < BB) {
        const int b = job;
        float* s_red = (float*)smem;             // [256]
        float* s_lev = s_red + 256;              // [64]
        unsigned int* s_cnt = (unsigned int*)(s_lev + 64);  // [64]

        float term = 0.0f;
        {
            unsigned int c = 0;
            #pragma unroll
            for (int p = 0; p < BPB; p++)
                c += g_hist_parts[(b * BPB + p) * 256 + tid];
            float nh = (float)c * (1.0f / 65536.0f);
            g_feats[b * SD + tid] = nh;
            term = -(nh * log2f(nh + 1e-10f));
        }
        s_red[tid] = term;
        if (tid < 64) {
            s_lev[tid] = (tid == 63) ? 8.0f : (float)tid * (8.0f / 63.0f);
            s_cnt[tid] = 0u;
        }
        __syncthreads();
        for (int s = 128; s; s >>= 1) {
            if (tid < s) s_red[tid] += s_red[tid + s];
            __syncthreads();
        }
        if (tid == 0) g_feats[b * SD + 256] = s_red[0];

        for (int i = tid; i < NW; i += 256) {
            float h = g_went[b * NW + i];
            int lo = 0, hi = 63;
            while (lo < hi) {
                int mid = (lo + hi) >> 1;
                if (h <= s_lev[mid]) hi = mid; else lo = mid + 1;
            }
            atomicAdd(&s_cnt[lo], 1u);
        }
        __syncthreads();
        if (tid < 64) {
            unsigned int sum = 0;
            for (int k = 0; k <= tid; k++) sum += s_cnt[k];
            g_feats[b * SD + 257 + tid] = (float)sum / 2047.0f;
        }
    } else {
        // warm L2 with all three weight matrices
        const int tg = (job - BB) * 256 + tid;   // 0..49151
        const int stride = (GRID2 - BB) * 256;
        float acc = 0.f;
        const int n1 = (SD * HID) / 4, n2 = (HID * HID) / 4, n3 = (HID * DM) / 4;
        for (int i = tg; i < n1; i += stride) {
            float4 v = *(const float4*)&W1[i * 4];
            acc += v.x + v.y + v.z + v.w;
        }
        for (int i = tg; i < n2; i += stride) {
            float4 v = *(const float4*)&W2[i * 4];
            acc += v.x + v.y + v.z + v.w;
        }
        for (int i = tg; i < n3; i += stride) {
            float4 v = *(const float4*)&W3[i * 4];
            acc += v.x + v.y + v.z + v.w;
        }
        if (__float_as_uint(acc) == 0xdeadbeefu) g_sink = acc;
    }

    grid_sync(1 * GRID2);
    gemm_phase<1>(W1, smem);
    grid_sync(2 * GRID2);
    if (job < BB) ln_phase<1>(b1, g1, be1, smem);
    grid_sync(3 * GRID2);
    gemm_phase<2>(W2, smem);
    grid_sync(4 * GRID2);
    if (job < BB) ln_phase<2>(b2, g2, be2, smem);
    grid_sync(5 * GRID2);
    gemm_phase<3>(W3, smem);
    grid_sync(6 * GRID2);

    // ---- finalize: out = sum(g_outp) + b3 (blocks 0-63) ----
    if (job < BB) {
        const int i = job * 256 + tid;
        float v = b3[i & (DM - 1)];
        #pragma unroll
        for (int s = 0; s < 8; s++) v += g_outp[s][i];
        out[i] = v;
    }
}

// ---------------- launch ----------------------------------------------------
extern "C" void kernel_launch(void* const* d_in, const int* in_sizes, int n_in,
                              void* d_out, int out_size) {
    const int*   x   = (const int*)d_in[0];
    const float* W1  = (const float*)d_in[1];
    const float* b1  = (const float*)d_in[2];
    const float* g1  = (const float*)d_in[3];
    const float* be1 = (const float*)d_in[4];
    const float* W2  = (const float*)d_in[5];
    const float* b2  = (const float*)d_in[6];
    const float* g2  = (const float*)d_in[7];
    const float* be2 = (const float*)d_in[8];
    const float* W3  = (const float*)d_in[9];
    const float* b3  = (const float*)d_in[10];
    float* out = (float*)d_out;

    cudaFuncSetAttribute(mlp_fused2, cudaFuncAttributeMaxDynamicSharedMemorySize, SMEM2);

    win_kernel<<<dim3(BPB, BB), 256>>>(x);
    mlp_fused2<<<GRID2, 256, SMEM2>>>(W1, b1, g1, be1, W2, b2, g2, be2, W3, b3, out);
}

// round 10
// speedup vs baseline: 2.0406x; 2.0406x over previous
#include <cuda_runtime.h>
#include <cuda_bf16.h>
#include <cuda_pipeline.h>
#include <math.h>

#define BB   64
#define LL   65536
#define NW   2047
#define WPB  128
#define BPB  16
#define SPAN_MAX 4128
#define HID  512
#define DM   256
#define SD   321

#define GRID2 128
// dynamic smem layout (bytes)
#define OFF_W1 0
#define OFF_W2 49152
#define OFF_W3 114688
#define OFF_A  147456
#define OFF_MISC 152576
#define SMEM2  154624

// ---------------- scratch (__device__ globals; no allocation allowed) -------
__device__ unsigned int g_hist_parts[BB * BPB * 256];
__device__ float g_went[BB * NW];
__device__ float g_feats[BB * SD];
__device__ float g_z1p[4][BB * HID];
__device__ float g_z2p[4][BB * HID];
__device__ float g_outp[8][BB * DM];
__device__ float g_a2[BB * HID];
__device__ float g_a3[BB * HID];
__device__ unsigned int g_bar;

// ---------------- Kernel A: windowed entropies + global hist partials -------
__global__ void __launch_bounds__(256) win_kernel(const int* __restrict__ x) {
    const int b    = blockIdx.y;
    const int blk  = blockIdx.x;
    const int tid  = threadIdx.x;
    const int lane = tid & 31;
    const int warp = tid >> 5;

    if (blk == 0 && b == 0 && tid == 0) g_bar = 0u;   // reset grid barrier

    const int wstart = blk * WPB;
    const int wcount = min(WPB, NW - wstart);
    const int span   = (wcount - 1) * 32 + 64;
    const long base  = (long)b * LL + (long)blk * (WPB * 32);

    __shared__ __align__(16) unsigned char s_x[SPAN_MAX + 32];
    __shared__ unsigned int  s_hist[8][64];   // packed u8 counts (4 per word)
    __shared__ unsigned int  s_part[256];
    __shared__ float         s_lut[65];

    if (tid < 256) s_part[tid] = 0u;
    if (tid <= 64) {
        if (tid == 0) s_lut[0] = 0.0f;
        else {
            float p = (float)tid * (1.0f / 64.0f);
            float t = -(p * log2f(p + 1e-10f));
            s_lut[tid] = t / (float)tid;
        }
    }
    {
        const int4* xv = (const int4*)(x + base);
        uchar4* sv = (uchar4*)s_x;
        const int n4 = span >> 2;
        for (int i = tid; i < n4; i += 256) {
            int4 v = xv[i];
            sv[i] = make_uchar4((unsigned char)min(max(v.x, 0), 255),
                                (unsigned char)min(max(v.y, 0), 255),
                                (unsigned char)min(max(v.z, 0), 255),
                                (unsigned char)min(max(v.w, 0), 255));
        }
    }
    __syncthreads();

    for (int i = tid; i < 4096; i += 256)
        atomicAdd(&s_part[s_x[i]], 1u);

    unsigned int* hist = s_hist[warp];
    for (int wi = warp; wi < wcount; wi += 8) {
        const int off = wi * 32;
        hist[lane]      = 0u;
        hist[lane + 32] = 0u;
        __syncwarp();
        const int va = s_x[off + lane];
        const int vb = s_x[off + 32 + lane];
        atomicAdd(&hist[va >> 2], 1u << ((va & 3) << 3));
        atomicAdd(&hist[vb >> 2], 1u << ((vb & 3) << 3));
        __syncwarp();
        const unsigned ca = (hist[va >> 2] >> ((va & 3) << 3)) & 0xFFu;
        const unsigned cb = (hist[vb >> 2] >> ((vb & 3) << 3)) & 0xFFu;
        float h = s_lut[ca] + s_lut[cb];
        #pragma unroll
        for (int o = 16; o; o >>= 1) h += __shfl_xor_sync(0xffffffffu, h, o);
        if (lane == 0) g_went[b * NW + wstart + wi] = h;
    }

    __syncthreads();
    if (tid < 256) g_hist_parts[(b * BPB + blk) * 256 + tid] = s_part[tid];
}

// ---------------- persistent fused feat + MLP --------------------------------
__device__ __forceinline__ void grid_sync(unsigned int target) {
    __syncthreads();
    if (threadIdx.x == 0) {
        __threadfence();
        atomicAdd(&g_bar, 1u);
        volatile unsigned int* p = &g_bar;
        while (*p < target) {}
        __threadfence();
    }
    __syncthreads();
}

// job decode per mode
template <int MODE>
__device__ __forceinline__ void job_decode(int job, int& ct, int& rg, int& ks) {
    if (MODE == 3) { ct = job & 1; rg = (job >> 1) & 7; ks = job >> 4; }
    else           { ct = job & 3; rg = (job >> 2) & 7; ks = job >> 5; }
}

// cp.async prefetch of this block's W tile for MODE into its smem region.
// Tile: CH rows x 128 cols, contiguous [CH][128] floats.
template <int MODE>
__device__ __forceinline__ void prefetch_w(const float* __restrict__ W, char* smem) {
    constexpr int CH = (MODE == 1) ? 96 : ((MODE == 2) ? 128 : 64);
    constexpr int N  = (MODE == 3) ? DM : HID;
    constexpr int K  = (MODE == 1) ? SD : HID;
    constexpr int NCHUNK = CH * 32;          // 16B chunks in tile

    char* dst_base = smem + ((MODE == 1) ? OFF_W1 : ((MODE == 2) ? OFF_W2 : OFF_W3));
    int ct, rg, ks;
    job_decode<MODE>(blockIdx.x, ct, rg, ks);
    const int c0 = ct * 128, k0 = ks * CH;

    const int tid = threadIdx.x;
    #pragma unroll
    for (int i = 0; i < NCHUNK / 256; i++) {
        const int c  = tid + i * 256;
        const int kr = c >> 5;               // row within tile
        const int cb = (c & 31) * 16;        // byte offset within row (512B)
        int ksrc = k0 + kr;
        if (MODE == 1 && ksrc >= K) ksrc = K - 1;   // clamp; A is zero there
        const char* src = (const char*)W + (long)ksrc * (N * 4) + (long)c0 * 4 + cb;
        __pipeline_memcpy_async(dst_base + c * 16, src, 16);
    }
    __pipeline_commit();
}

// GEMM phase: 128 jobs, tile 8r x 128c x CH-k, thread 2x2. W already in smem.
// MODE 1: A=g_feats K=321 CH=96  ks4 -> g_z1p[4]
// MODE 2: A=g_a2   K=512 CH=128 ks4 -> g_z2p[4]
// MODE 3: A=g_a3   K=512 CH=64  ks8 -> g_outp[8] (N=256)
template <int MODE>
__device__ void gemm_phase(char* smem) {
    constexpr int CH = (MODE == 1) ? 96 : ((MODE == 2) ? 128 : 64);
    constexpr int N  = (MODE == 3) ? DM : HID;
    constexpr int K  = (MODE == 1) ? SD : HID;

    int ct, rg, ks;
    job_decode<MODE>(blockIdx.x, ct, rg, ks);
    const int c0 = ct * 128, r0 = rg * 8, k0 = ks * CH;

    float* s_w = (float*)(smem + ((MODE == 1) ? OFF_W1 : ((MODE == 2) ? OFF_W2 : OFF_W3)));
    float* s_a = (float*)(smem + OFF_A);     // [CH][10]

    const int tid = threadIdx.x;

    // wait for this mode's prefetch group
    __pipeline_wait_prior(3 - MODE);

    // A tile: 8 rows x CH k, transposed
    {
        const float* A = (MODE == 1) ? g_feats : ((MODE == 2) ? g_a2 : g_a3);
        const int astr = (MODE == 1) ? SD : HID;
        for (int idx = tid; idx < 8 * CH; idx += 256) {
            const int r = idx / CH, k = idx - r * CH;
            float v = 0.f;
            if (MODE != 1 || (k0 + k) < K) v = A[(r0 + r) * astr + k0 + k];
            s_a[k * 10 + r] = v;
        }
    }
    __syncthreads();

    const int rp = tid >> 6, cp = tid & 63;
    float a00 = 0.f, a01 = 0.f, a10 = 0.f, a11 = 0.f;
    #pragma unroll 8
    for (int kk = 0; kk < CH; kk++) {
        const float2 wv = *(const float2*)&s_w[kk * 128 + cp * 2];
        const float2 av = *(const float2*)&s_a[kk * 10 + rp * 2];
        a00 = fmaf(av.x, wv.x, a00);
        a01 = fmaf(av.x, wv.y, a01);
        a10 = fmaf(av.y, wv.x, a10);
        a11 = fmaf(av.y, wv.y, a11);
    }
    __syncthreads();

    float* OP = (MODE == 1) ? &g_z1p[0][0] : ((MODE == 2) ? &g_z2p[0][0] : &g_outp[0][0]);
    const long base = (long)ks * (BB * N);
    const int r = r0 + rp * 2, cc = c0 + cp * 2;
    *(float2*)&OP[base + (long)r * N + cc]       = make_float2(a00, a01);
    *(float2*)&OP[base + (long)(r + 1) * N + cc] = make_float2(a10, a11);
}

// LN phase: blocks 0-63, block = row. 256 threads, 2 features each. 4 partials.
template <int LAYER>
__device__ void ln_phase(const float* __restrict__ bias,
                         const float* __restrict__ gam,
                         const float* __restrict__ bet, char* smem) {
    const float* P = (LAYER == 1) ? &g_z1p[0][0] : &g_z2p[0][0];
    float* outA    = (LAYER == 1) ? g_a2 : g_a3;
    float* s_r     = (float*)(smem + OFF_MISC);    // [8]
    float* s_tot   = s_r + 8;

    const int r    = blockIdx.x;
    const int tid  = threadIdx.x;
    const int lane = tid & 31;
    const int wid  = tid >> 5;
    const int k1 = tid, k2 = tid + 256;

    float z1 = bias[k1], z2 = bias[k2];
    #pragma unroll
    for (int s = 0; s < 4; s++) {
        z1 += P[(long)s * (BB * HID) + r * HID + k1];
        z2 += P[(long)s * (BB * HID) + r * HID + k2];
    }

    float t = z1 + z2;
    #pragma unroll
    for (int o = 16; o; o >>= 1) t += __shfl_xor_sync(0xffffffffu, t, o);
    if (lane == 0) s_r[wid] = t;
    __syncthreads();
    if (tid == 0) {
        float u = 0.f;
        #pragma unroll
        for (int i = 0; i < 8; i++) u += s_r[i];
        *s_tot = u;
    }
    __syncthreads();
    const float mu = *s_tot * (1.0f / 512.0f);

    const float d1 = z1 - mu, d2 = z2 - mu;
    float v = d1 * d1 + d2 * d2;
    #pragma unroll
    for (int o = 16; o; o >>= 1) v += __shfl_xor_sync(0xffffffffu, v, o);
    if (lane == 0) s_r[wid] = v;
    __syncthreads();
    if (tid == 0) {
        float u = 0.f;
        #pragma unroll
        for (int i = 0; i < 8; i++) u += s_r[i];
        *s_tot = u;
    }
    __syncthreads();
    const float rstd = rsqrtf(*s_tot * (1.0f / 512.0f) + 1e-5f);

    outA[r * HID + k1] = fmaxf(d1 * rstd * gam[k1] + bet[k1], 0.0f);
    outA[r * HID + k2] = fmaxf(d2 * rstd * gam[k2] + bet[k2], 0.0f);
}

__global__ void __launch_bounds__(256, 1) mlp_fused3(
    const float* __restrict__ W1, const float* __restrict__ b1,
    const float* __restrict__ g1, const float* __restrict__ be1,
    const float* __restrict__ W2, const float* __restrict__ b2,
    const float* __restrict__ g2, const float* __restrict__ be2,
    const float* __restrict__ W3, const float* __restrict__ b3,
    float* __restrict__ out) {
    extern __shared__ __align__(16) char smem[];
    const int job = blockIdx.x;
    const int tid = threadIdx.x;

    // ---- prefetch ALL three W tiles via cp.async (weights-only dependency) --
    prefetch_w<1>(W1, smem);
    prefetch_w<2>(W2, smem);
    prefetch_w<3>(W3, smem);

    // ---- phase A: features (blocks 0-63) ----
    if (job < BB) {
        const int b = job;
        float* s_red = (float*)(smem + OFF_MISC);             // reuse misc? too small
        // feat needs 256+64 floats + 64 uints = 1536B -> use misc region (2KB)
        float* s_lev = s_red + 0;  // placeholder (re-laid below)
        // lay out: s_cnt [64] at misc, s_lev [64] after, and do the 256-reduce
        // via shuffles to avoid a 1KB buffer.
        unsigned int* s_cnt = (unsigned int*)(smem + OFF_MISC);         // [64]
        s_lev = (float*)(smem + OFF_MISC + 256);                        // [64]
        float* s_wred = (float*)(smem + OFF_MISC + 512);                // [8]

        float term = 0.0f;
        {
            unsigned int c = 0;
            #pragma unroll
            for (int p = 0; p < BPB; p++)
                c += g_hist_parts[(b * BPB + p) * 256 + tid];
            float nh = (float)c * (1.0f / 65536.0f);
            g_feats[b * SD + tid] = nh;
            term = -(nh * log2f(nh + 1e-10f));
        }
        if (tid < 64) {
            s_lev[tid] = (tid == 63) ? 8.0f : (float)tid * (8.0f / 63.0f);
            s_cnt[tid] = 0u;
        }
        // block-reduce term via shuffles
        {
            const int lane = tid & 31, wid = tid >> 5;
            float t = term;
            #pragma unroll
            for (int o = 16; o; o >>= 1) t += __shfl_xor_sync(0xffffffffu, t, o);
            if (lane == 0) s_wred[wid] = t;
            __syncthreads();
            if (tid == 0) {
                float u = 0.f;
                #pragma unroll
                for (int i = 0; i < 8; i++) u += s_wred[i];
                g_feats[b * SD + 256] = u;
            }
        }

        for (int i = tid; i < NW; i += 256) {
            float h = g_went[b * NW + i];
            int lo = 0, hi = 63;
            while (lo < hi) {
                int mid = (lo + hi) >> 1;
                if (h <= s_lev[mid]) hi = mid; else lo = mid + 1;
            }
            atomicAdd(&s_cnt[lo], 1u);
        }
        __syncthreads();
        if (tid < 64) {
            unsigned int sum = 0;
            for (int k = 0; k <= tid; k++) sum += s_cnt[k];
            g_feats[b * SD + 257 + tid] = (float)sum / 2047.0f;
        }
    }

    grid_sync(1 * GRID2);
    gemm_phase<1>(smem);
    grid_sync(2 * GRID2);
    if (job < BB) ln_phase<1>(b1, g1, be1, smem);
    grid_sync(3 * GRID2);
    gemm_phase<2>(smem);
    grid_sync(4 * GRID2);
    if (job < BB) ln_phase<2>(b2, g2, be2, smem);
    grid_sync(5 * GRID2);
    gemm_phase<3>(smem);
    grid_sync(6 * GRID2);

    // ---- finalize: out = sum(g_outp[8]) + b3 (blocks 0-63) ----
    if (job < BB) {
        const int i = job * 256 + tid;
        float v = b3[i & (DM - 1)];
        #pragma unroll
        for (int s = 0; s < 8; s++) v += g_outp[s][i];
        out[i] = v;
    }
}

// ---------------- launch ----------------------------------------------------
extern "C" void kernel_launch(void* const* d_in, const int* in_sizes, int n_in,
                              void* d_out, int out_size) {
    const int*   x   = (const int*)d_in[0];
    const float* W1  = (const float*)d_in[1];
    const float* b1  = (const float*)d_in[2];
    const float* g1  = (const float*)d_in[3];
    const float* be1 = (const float*)d_in[4];
    const float* W2  = (const float*)d_in[5];
    const float* b2  = (const float*)d_in[6];
    const float* g2  = (const float*)d_in[7];
    const float* be2 = (const float*)d_in[8];
    const float* W3  = (const float*)d_in[9];
    const float* b3  = (const float*)d_in[10];
    float* out = (float*)d_out;

    cudaFuncSetAttribute(mlp_fused3, cudaFuncAttributeMaxDynamicSharedMemorySize, SMEM2);

    win_kernel<<<dim3(BPB, BB), 256>>>(x);
    mlp_fused3<<<GRID2, 256, SMEM2>>>(W1, b1, g1, be1, W2, b2, g2, be2, W3, b3, out);
}

// round 11
// speedup vs baseline: 2.2333x; 1.0944x over previous
#include <cuda_runtime.h>
#include <cuda_bf16.h>
#include <cuda_pipeline.h>
#include <math.h>

#define BB   64
#define LL   65536
#define NW   2047
#define WPB  128
#define BPB  16
#define SPAN_MAX 4128
#define HID  512
#define DM   256
#define SD   321

#define GRID2 128
// dynamic smem layout (bytes)
#define OFF_W1 0
#define OFF_W2 49152
#define OFF_W3 114688
#define OFF_A  147456
#define OFF_MISC 152576
#define SMEM2  154624

// ---------------- scratch (__device__ globals; no allocation allowed) -------
__device__ unsigned int g_hist_parts[BB * BPB * 256];
__device__ float g_went[BB * NW];
__device__ float g_feats[BB * SD];
__device__ float g_z1p[4][BB * HID];
__device__ float g_z2p[4][BB * HID];
__device__ float g_outp[8][BB * DM];
// dataflow counters: [0]=feat rows, [1]=z1 jobs, [2]=z2 jobs, [3]=out jobs (per rowgroup)
__device__ unsigned int g_cnt[4][8];

// ---------------- Kernel A: windowed entropies + global hist partials -------
__global__ void __launch_bounds__(256) win_kernel(const int* __restrict__ x) {
    const int b    = blockIdx.y;
    const int blk  = blockIdx.x;
    const int tid  = threadIdx.x;
    const int lane = tid & 31;
    const int warp = tid >> 5;

    if (blk == 0 && b == 0 && tid < 32) ((unsigned int*)g_cnt)[tid] = 0u;

    const int wstart = blk * WPB;
    const int wcount = min(WPB, NW - wstart);
    const int span   = (wcount - 1) * 32 + 64;
    const long base  = (long)b * LL + (long)blk * (WPB * 32);

    __shared__ __align__(16) unsigned char s_x[SPAN_MAX + 32];
    __shared__ unsigned int  s_hist[8][64];   // packed u8 counts (4 per word)
    __shared__ unsigned int  s_part[256];
    __shared__ float         s_lut[65];

    if (tid < 256) s_part[tid] = 0u;
    if (tid <= 64) {
        if (tid == 0) s_lut[0] = 0.0f;
        else {
            float p = (float)tid * (1.0f / 64.0f);
            float t = -(p * log2f(p + 1e-10f));
            s_lut[tid] = t / (float)tid;
        }
    }
    {
        const int4* xv = (const int4*)(x + base);
        uchar4* sv = (uchar4*)s_x;
        const int n4 = span >> 2;
        for (int i = tid; i < n4; i += 256) {
            int4 v = xv[i];
            sv[i] = make_uchar4((unsigned char)min(max(v.x, 0), 255),
                                (unsigned char)min(max(v.y, 0), 255),
                                (unsigned char)min(max(v.z, 0), 255),
                                (unsigned char)min(max(v.w, 0), 255));
        }
    }
    __syncthreads();

    for (int i = tid; i < 4096; i += 256)
        atomicAdd(&s_part[s_x[i]], 1u);

    unsigned int* hist = s_hist[warp];
    for (int wi = warp; wi < wcount; wi += 8) {
        const int off = wi * 32;
        hist[lane]      = 0u;
        hist[lane + 32] = 0u;
        __syncwarp();
        const int va = s_x[off + lane];
        const int vb = s_x[off + 32 + lane];
        atomicAdd(&hist[va >> 2], 1u << ((va & 3) << 3));
        atomicAdd(&hist[vb >> 2], 1u << ((vb & 3) << 3));
        __syncwarp();
        const unsigned ca = (hist[va >> 2] >> ((va & 3) << 3)) & 0xFFu;
        const unsigned cb = (hist[vb >> 2] >> ((vb & 3) << 3)) & 0xFFu;
        float h = s_lut[ca] + s_lut[cb];
        #pragma unroll
        for (int o = 16; o; o >>= 1) h += __shfl_xor_sync(0xffffffffu, h, o);
        if (lane == 0) g_went[b * NW + wstart + wi] = h;
    }

    __syncthreads();
    if (tid < 256) g_hist_parts[(b * BPB + blk) * 256 + tid] = s_part[tid];
}

// ---------------- dataflow sync helpers --------------------------------------
__device__ __forceinline__ void publish(unsigned int* c) {
    __syncthreads();
    __threadfence();
    if (threadIdx.x == 0) atomicAdd(c, 1u);
}
__device__ __forceinline__ void waitc(unsigned int* c, unsigned int tgt) {
    __syncthreads();
    if (threadIdx.x == 0) {
        volatile unsigned int* p = c;
        while (*p < tgt) {}
        __threadfence();
    }
    __syncthreads();
}

// job decode
template <int MODE>
__device__ __forceinline__ void job_decode(int job, int& ct, int& rg, int& ks) {
    if (MODE == 3) { ct = job & 1; rg = (job >> 1) & 7; ks = job >> 4; }
    else           { ct = job & 3; rg = (job >> 2) & 7; ks = job >> 5; }
}

// cp.async W-tile prefetch. Tile: CH rows x 128 cols.
template <int MODE>
__device__ __forceinline__ void prefetch_w(const float* __restrict__ W, char* smem) {
    constexpr int CH = (MODE == 1) ? 96 : ((MODE == 2) ? 128 : 64);
    constexpr int N  = (MODE == 3) ? DM : HID;
    constexpr int K  = (MODE == 1) ? SD : HID;
    constexpr int NCHUNK = CH * 32;

    char* dst_base = smem + ((MODE == 1) ? OFF_W1 : ((MODE == 2) ? OFF_W2 : OFF_W3));
    int ct, rg, ks;
    job_decode<MODE>(blockIdx.x, ct, rg, ks);
    const int c0 = ct * 128, k0 = ks * CH;

    const int tid = threadIdx.x;
    #pragma unroll
    for (int i = 0; i < NCHUNK / 256; i++) {
        const int c  = tid + i * 256;
        const int kr = c >> 5;
        const int cb = (c & 31) * 16;
        int ksrc = k0 + kr;
        if (MODE == 1 && ksrc >= K) ksrc = K - 1;   // clamp; A is zero there
        const char* src = (const char*)W + (long)ksrc * (N * 4) + (long)c0 * 4 + cb;
        __pipeline_memcpy_async(dst_base + c * 16, src, 16);
    }
    __pipeline_commit();
}

// GEMM stage with dataflow waits. 128 jobs each.
// MODE 1: A=g_feats (K=321) CH=96  ks4 -> g_z1p[4]
// MODE 2: A=relu(LN(sum z1p + b1)) CH=128 ks4 -> g_z2p[4]
// MODE 3: A=relu(LN(sum z2p + b2)) CH=64  ks8 -> g_outp[8]  (N=256)
template <int MODE>
__device__ void mlp_gemm(char* smem,
                         const float* __restrict__ bias,
                         const float* __restrict__ gam,
                         const float* __restrict__ bet) {
    constexpr int CH = (MODE == 1) ? 96 : ((MODE == 2) ? 128 : 64);
    constexpr int N  = (MODE == 3) ? DM : HID;
    constexpr int K  = (MODE == 1) ? SD : HID;

    int ct, rg, ks;
    job_decode<MODE>(blockIdx.x, ct, rg, ks);
    const int c0 = ct * 128, r0 = rg * 8, k0 = ks * CH;

    // wait for upstream rowgroup completion
    if (MODE == 1) waitc(&g_cnt[0][rg], 8);
    else           waitc(&g_cnt[MODE - 1][rg], 16);

    float* s_w = (float*)(smem + ((MODE == 1) ? OFF_W1 : ((MODE == 2) ? OFF_W2 : OFF_W3)));
    float* s_a = (float*)(smem + OFF_A);     // [CH][10]

    const int tid  = threadIdx.x;
    const int lane = tid & 31;
    const int w    = tid >> 5;

    __pipeline_wait_prior(3 - MODE);

    // ---- stage A ----
    if (MODE == 1) {
        for (int idx = tid; idx < 8 * CH; idx += 256) {
            const int r = idx / CH, k = idx - r * CH;
            float v = 0.f;
            if ((k0 + k) < K) v = g_feats[(r0 + r) * SD + k0 + k];
            s_a[k * 10 + r] = v;
        }
    } else {
        // reduce partials + bias + LN + relu, warp w handles row r0+w
        const float* P = (MODE == 2) ? &g_z1p[0][0] : &g_z2p[0][0];
        const int r = r0 + w;
        float zv[16];
        float sum = 0.f;
        #pragma unroll
        for (int i = 0; i < 16; i++) {
            const int k = lane + 32 * i;
            float z = bias[k];
            #pragma unroll
            for (int s = 0; s < 4; s++) z += P[(long)s * (BB * HID) + r * HID + k];
            zv[i] = z; sum += z;
        }
        #pragma unroll
        for (int o = 16; o; o >>= 1) sum += __shfl_xor_sync(0xffffffffu, sum, o);
        const float mu = sum * (1.0f / 512.0f);
        float vs = 0.f;
        #pragma unroll
        for (int i = 0; i < 16; i++) { const float d = zv[i] - mu; vs += d * d; }
        #pragma unroll
        for (int o = 16; o; o >>= 1) vs += __shfl_xor_sync(0xffffffffu, vs, o);
        const float rstd = rsqrtf(vs * (1.0f / 512.0f) + 1e-5f);
        #pragma unroll
        for (int j = 0; j < CH / 32; j++) {
            const int i = (k0 >> 5) + j;
            const int k = lane + 32 * i;
            const float hv = (zv[i] - mu) * rstd * gam[k] + bet[k];
            s_a[(k - k0) * 10 + w] = fmaxf(hv, 0.0f);
        }
    }
    __syncthreads();

    // ---- compute: 2x2 register tile ----
    const int rp = tid >> 6, cp = tid & 63;
    float a00 = 0.f, a01 = 0.f, a10 = 0.f, a11 = 0.f;
    #pragma unroll 8
    for (int kk = 0; kk < CH; kk++) {
        const float2 wv = *(const float2*)&s_w[kk * 128 + cp * 2];
        const float2 av = *(const float2*)&s_a[kk * 10 + rp * 2];
        a00 = fmaf(av.x, wv.x, a00);
        a01 = fmaf(av.x, wv.y, a01);
        a10 = fmaf(av.y, wv.x, a10);
        a11 = fmaf(av.y, wv.y, a11);
    }

    float* OP = (MODE == 1) ? &g_z1p[0][0] : ((MODE == 2) ? &g_z2p[0][0] : &g_outp[0][0]);
    const long base = (long)ks * (BB * N);
    const int r = r0 + rp * 2, cc = c0 + cp * 2;
    *(float2*)&OP[base + (long)r * N + cc]       = make_float2(a00, a01);
    *(float2*)&OP[base + (long)(r + 1) * N + cc] = make_float2(a10, a11);

    publish(&g_cnt[MODE][rg]);
}

__global__ void __launch_bounds__(256, 1) mlp_fused4(
    const float* __restrict__ W1, const float* __restrict__ b1,
    const float* __restrict__ g1, const float* __restrict__ be1,
    const float* __restrict__ W2, const float* __restrict__ b2,
    const float* __restrict__ g2, const float* __restrict__ be2,
    const float* __restrict__ W3, const float* __restrict__ b3,
    float* __restrict__ out) {
    extern __shared__ __align__(16) char smem[];
    const int job = blockIdx.x;
    const int tid = threadIdx.x;

    // prefetch all three W tiles (weights-only dependency)
    prefetch_w<1>(W1, smem);
    prefetch_w<2>(W2, smem);
    prefetch_w<3>(W3, smem);

    // ---- feat: blocks 0-63, one batch row each ----
    if (job < BB) {
        const int b = job;
        unsigned int* s_cnt = (unsigned int*)(smem + OFF_MISC);   // [64]
        float* s_lev  = (float*)(smem + OFF_MISC + 256);          // [64]
        float* s_wred = (float*)(smem + OFF_MISC + 512);          // [8]

        float term = 0.0f;
        {
            unsigned int c = 0;
            #pragma unroll
            for (int p = 0; p < BPB; p++)
                c += g_hist_parts[(b * BPB + p) * 256 + tid];
            float nh = (float)c * (1.0f / 65536.0f);
            g_feats[b * SD + tid] = nh;
            term = -(nh * log2f(nh + 1e-10f));
        }
        if (tid < 64) {
            s_lev[tid] = (tid == 63) ? 8.0f : (float)tid * (8.0f / 63.0f);
            s_cnt[tid] = 0u;
        }
        {
            const int lane = tid & 31, wid = tid >> 5;
            float t = term;
            #pragma unroll
            for (int o = 16; o; o >>= 1) t += __shfl_xor_sync(0xffffffffu, t, o);
            if (lane == 0) s_wred[wid] = t;
            __syncthreads();
            if (tid == 0) {
                float u = 0.f;
                #pragma unroll
                for (int i = 0; i < 8; i++) u += s_wred[i];
                g_feats[b * SD + 256] = u;
            }
        }

        for (int i = tid; i < NW; i += 256) {
            float h = g_went[b * NW + i];
            int lo = 0, hi = 63;
            while (lo < hi) {
                int mid = (lo + hi) >> 1;
                if (h <= s_lev[mid]) hi = mid; else lo = mid + 1;
            }
            atomicAdd(&s_cnt[lo], 1u);
        }
        __syncthreads();
        if (tid < 64) {
            unsigned int sum = 0;
            for (int k = 0; k <= tid; k++) sum += s_cnt[k];
            g_feats[b * SD + 257 + tid] = (float)sum / 2047.0f;
        }
        publish(&g_cnt[0][b >> 3]);
    }

    mlp_gemm<1>(smem, nullptr, nullptr, nullptr);
    mlp_gemm<2>(smem, b1, g1, be1);
    mlp_gemm<3>(smem, b2, g2, be2);

    // ---- finalize: blocks 0-63, one row each ----
    if (job < BB) {
        waitc(&g_cnt[3][job >> 3], 16);
        const int i = job * DM + tid;
        float v = b3[tid];
        #pragma unroll
        for (int s = 0; s < 8; s++) v += g_outp[s][i];
        out[i] = v;
    }
}

// ---------------- launch ----------------------------------------------------
extern "C" void kernel_launch(void* const* d_in, const int* in_sizes, int n_in,
                              void* d_out, int out_size) {
    const int*   x   = (const int*)d_in[0];
    const float* W1  = (const float*)d_in[1];
    const float* b1  = (const float*)d_in[2];
    const float* g1  = (const float*)d_in[3];
    const float* be1 = (const float*)d_in[4];
    const float* W2  = (const float*)d_in[5];
    const float* b2  = (const float*)d_in[6];
    const float* g2  = (const float*)d_in[7];
    const float* be2 = (const float*)d_in[8];
    const float* W3  = (const float*)d_in[9];
    const float* b3  = (const float*)d_in[10];
    float* out = (float*)d_out;

    cudaFuncSetAttribute(mlp_fused4, cudaFuncAttributeMaxDynamicSharedMemorySize, SMEM2);

    win_kernel<<<dim3(BPB, BB), 256>>>(x);
    mlp_fused4<<<GRID2, 256, SMEM2>>>(W1, b1, g1, be1, W2, b2, g2, be2, W3, b3, out);
}